// round 13
// baseline (speedup 1.0000x reference)
#include <cuda_runtime.h>
#include <cuda_bf16.h>
#include <cstdint>

// ---------------- problem constants ----------------
#define B_   16
#define C_   64
#define H_   192
#define W_   192
#define NPIX (H_ * W_)

// ---------------- tiling ----------------
#define TRR 6                  // tile rows
#define TC  32                 // tile cols (192 px, 64 oc per tile)
#define HRR 8                  // halo rows
#define HC  34                 // halo cols
#define ROWB  272              // 34 * 8 B (word pair e0,e1)
#define SLOTB 2208             // 8*272=2176 + 32 pad (p_ bank stride = 8)
#define IMGB  (16 * SLOTB)     // 35328 B per image (hi or lo)
#define XBYTES (2 * IMGB)      // 70656
#define WBYTES 147456          // 9 taps x 1024 uint4 (bf16 A-fragments, hi+lo)
#define SMEM_BYTES (WBYTES + XBYTES)   // 218112 -> 1 CTA/SM
#define THREADS 384            // 12 warps = 6 rows x 2 oc-halves
#define TPB 192                // tiles per batch (32 row-tiles x 6 col-tiles)
#define CPB 9                  // CTAs per batch (144 CTAs total)

// Pre-packed W fragments: [b][tap][kf][hl][mf][lane] uint4 (mma A-frag order)
__device__ uint4 g_wfrag[B_ * 9 * 4 * 2 * 4 * 32];

// ---------------- helpers ----------------
__device__ __forceinline__ uint32_t smem_u32(const void* p) {
    uint32_t a;
    asm("{ .reg .u64 t; cvta.to.shared.u64 t, %1; cvt.u32.u64 %0, t; }" : "=r"(a) : "l"(p));
    return a;
}
__device__ __forceinline__ uint32_t cvt2(float lo, float hi) {
    uint32_t r;
    asm("cvt.rn.satfinite.bf16x2.f32 %0, %1, %2;" : "=r"(r) : "f"(hi), "f"(lo));
    return r;
}
__device__ __forceinline__ void split2(float v0, float v1, uint32_t& h2, uint32_t& l2) {
    h2 = cvt2(v0, v1);
    float h0 = __uint_as_float(h2 << 16);
    float h1 = __uint_as_float(h2 & 0xFFFF0000u);
    l2 = cvt2(v0 - h0, v1 - h1);
}
__device__ __forceinline__ void sts32(uint32_t a, uint32_t v) {
    asm volatile("st.shared.b32 [%0], %1;" :: "r"(a), "r"(v) : "memory");
}
__device__ __forceinline__ void sts128(uint32_t a, uint4 v) {
    asm volatile("st.shared.v4.b32 [%0], {%1,%2,%3,%4};"
                 :: "r"(a), "r"(v.x), "r"(v.y), "r"(v.z), "r"(v.w) : "memory");
}
__device__ __forceinline__ void lds128(uint4& v, uint32_t a) {
    asm volatile("ld.shared.v4.b32 {%0,%1,%2,%3}, [%4];"
                 : "=r"(v.x), "=r"(v.y), "=r"(v.z), "=r"(v.w) : "r"(a));
}
__device__ __forceinline__ void mma16816(float* c, const uint4& a, uint32_t b0, uint32_t b1) {
    asm volatile(
        "mma.sync.aligned.m16n8k16.row.col.f32.bf16.bf16.f32 "
        "{%0,%1,%2,%3}, {%4,%5,%6,%7}, {%8,%9}, {%0,%1,%2,%3};"
        : "+f"(c[0]), "+f"(c[1]), "+f"(c[2]), "+f"(c[3])
        : "r"(a.x), "r"(a.y), "r"(a.z), "r"(a.w), "r"(b0), "r"(b1));
}

// ---------------- prep: interpolate + split + pack W fragments ----------------
__global__ void prep_w(const float* __restrict__ W0, const float* __restrict__ W1,
                       const float* __restrict__ DoT)
{
    const int tap = blockIdx.x;
    const int b   = blockIdx.y;
    const float d = DoT[b], od = 1.0f - d;

    const int t    = threadIdx.x;
    const int kf   = t >> 7;
    const int mf   = (t >> 5) & 3;
    const int lane = t & 31;
    const int m    = mf * 16 + (lane >> 2);
    const int k    = kf * 16 + (lane & 3) * 2;

    float v[4][2];
    #pragma unroll
    for (int r = 0; r < 4; r++) {
        const int oc = m + (r & 1) * 8;
        const int ci = k + (r >> 1) * 8;
        const size_t g0 = (size_t)(oc * C_ + ci) * 9 + tap;
        v[r][0] = od * W0[g0] + d * W1[g0];
        v[r][1] = od * W0[g0 + 9] + d * W1[g0 + 9];
    }
    uint4 hi, lo;
    uint32_t* hp = &hi.x;
    uint32_t* lp = &lo.x;
    #pragma unroll
    for (int r = 0; r < 4; r++) split2(v[r][0], v[r][1], hp[r], lp[r]);

    const size_t base = ((((size_t)(b * 9 + tap) * 4 + kf) * 2) * 4 + mf) * 32 + lane;
    g_wfrag[base]       = hi;
    g_wfrag[base + 128] = lo;
}

// ---------------- main kernel: persistent CTA, smem-resident weights ----------------
__global__ __launch_bounds__(THREADS, 1)
void conv_mma(const float* __restrict__ x, float* __restrict__ y)
{
    extern __shared__ char smem[];
    const uint32_t ws = smem_u32(smem);        // weights [0, WBYTES)
    const uint32_t xs = ws + WBYTES;           // x tile  [WBYTES, WBYTES+XBYTES)

    const int tid  = threadIdx.x;
    const int wid  = tid >> 5;
    const int lane = tid & 31;
    const int row  = wid % 6;        // tile row
    const int oh   = wid / 6;        // oc half
    const int p_   = lane & 3;
    const int q    = lane >> 2;

    const int b  = blockIdx.x / CPB;
    const int k  = blockIdx.x % CPB;
    const int t0 = (k * TPB) / CPB;
    const int t1 = ((k + 1) * TPB) / CPB;

    const float* xb = x + (size_t)b * C_ * NPIX;
    float* yb       = y + (size_t)b * C_ * NPIX;

    // ---- one-time: this batch's full fragment set into smem ----
    {
        const uint4* wg = g_wfrag + (size_t)b * 9216;
        for (int i = tid; i < 9216; i += THREADS)
            sts128(ws + (uint32_t)i * 16, wg[i]);
    }

    const uint32_t thr_base = xs + (uint32_t)(p_ * SLOTB + q * 8);

    for (int tib = t0; tib < t1; tib++) {
        const int py0 = (tib / 6) * TRR;
        const int px0 = (tib % 6) * TC;

        // ---- serial fill: fp32 halo -> bf16 hi/lo split ----
        __syncthreads();   // prev tile reads done (first iter: weights visible)
        for (int idx = tid; idx < 32 * HRR * HC; idx += THREADS) {
            const int ci2 = idx / (HRR * HC);
            const int rem = idx - ci2 * (HRR * HC);
            const int r   = rem / HC;
            const int c   = rem - r * HC;
            const int gy  = py0 - 1 + r;
            const int gx  = px0 - 1 + c;
            float v0 = 0.f, v1 = 0.f;
            if ((unsigned)gy < H_ && (unsigned)gx < W_) {
                const float* p = xb + (size_t)(2 * ci2) * NPIX + gy * W_ + gx;
                v0 = p[0];
                v1 = p[NPIX];
            }
            uint32_t h2, l2;
            split2(v0, v1, h2, l2);
            const int kfi = ci2 >> 3, l = ci2 & 7, pp = l & 3, e = l >> 2;
            const uint32_t off = (uint32_t)((kfi * 4 + pp) * SLOTB + r * ROWB + c * 8 + e * 4);
            sts32(xs + off,        h2);
            sts32(xs + IMGB + off, l2);
        }
        __syncthreads();

        float acc[2][4][4];
        #pragma unroll
        for (int m = 0; m < 2; m++)
            #pragma unroll
            for (int cs = 0; cs < 4; cs++) {
                acc[m][cs][0] = 0.f; acc[m][cs][1] = 0.f;
                acc[m][cs][2] = 0.f; acc[m][cs][3] = 0.f;
            }

        // ---- mainloop: all operands from smem ----
        for (int tap = 0; tap < 9; tap++) {
            const int ky = tap / 3;
            const int kx = tap - ky * 3;
            const uint32_t wt = ws + (uint32_t)tap * 16384;
            const uint32_t tap_off = (uint32_t)((row + ky) * ROWB + kx * 8);

            #pragma unroll
            for (int kf = 0; kf < 4; kf++) {
                const uint32_t wk = wt + (uint32_t)kf * 4096 + (uint32_t)lane * 16;
                uint4 ah[2], al[2];
                lds128(ah[0], wk + (uint32_t)((oh * 2 + 0) * 32) * 16);
                lds128(ah[1], wk + (uint32_t)((oh * 2 + 1) * 32) * 16);
                lds128(al[0], wk + (uint32_t)((128 + (oh * 2 + 0) * 32)) * 16);
                lds128(al[1], wk + (uint32_t)((128 + (oh * 2 + 1) * 32)) * 16);
                const uint32_t a_base = thr_base + tap_off + (uint32_t)(kf * 4 * SLOTB);

                #pragma unroll
                for (int cs = 0; cs < 4; cs++) {
                    const uint32_t ad = a_base + cs * 64;
                    uint32_t bh0, bh1, bl0, bl1;
                    asm volatile("ld.shared.v2.b32 {%0,%1}, [%2];"
                                 : "=r"(bh0), "=r"(bh1) : "r"(ad));
                    asm volatile("ld.shared.v2.b32 {%0,%1}, [%2];"
                                 : "=r"(bl0), "=r"(bl1) : "r"(ad + IMGB));
                    mma16816(acc[0][cs], ah[0], bh0, bh1);
                    mma16816(acc[1][cs], ah[1], bh0, bh1);
                    mma16816(acc[0][cs], al[0], bh0, bh1);
                    mma16816(acc[1][cs], al[1], bh0, bh1);
                    mma16816(acc[0][cs], ah[0], bl0, bl1);
                    mma16816(acc[1][cs], ah[1], bl0, bl1);
                }
            }
        }

        // ---- epilogue ----
        const int gy = py0 + row;
        #pragma unroll
        for (int m = 0; m < 2; m++) {
            const int oc = (oh * 2 + m) * 16 + q;
            #pragma unroll
            for (int cs = 0; cs < 4; cs++) {
                const int gx = px0 + cs * 8 + 2 * p_;
                float2* o0 = (float2*)(yb + (size_t)oc * NPIX + gy * W_ + gx);
                *o0 = make_float2(acc[m][cs][0], acc[m][cs][1]);
                float2* o1 = (float2*)(yb + (size_t)(oc + 8) * NPIX + gy * W_ + gx);
                *o1 = make_float2(acc[m][cs][2], acc[m][cs][3]);
            }
        }
    }
}

// ---------------- launch ----------------
extern "C" void kernel_launch(void* const* d_in, const int* in_sizes, int n_in,
                              void* d_out, int out_size)
{
    const float* x   = (const float*)d_in[0];
    const float* DoT = (const float*)d_in[1];
    const float* W0  = (const float*)d_in[2];
    const float* W1  = (const float*)d_in[3];
    float* y = (float*)d_out;

    cudaFuncSetAttribute(conv_mma, cudaFuncAttributeMaxDynamicSharedMemorySize, SMEM_BYTES);

    prep_w<<<dim3(9, B_), 512>>>(W0, W1, DoT);
    // 144 persistent CTAs = 16 batches x 9; each covers 21-22 of its batch's 192 tiles
    conv_mma<<<B_ * CPB, THREADS, SMEM_BYTES>>>(x, y);
}

// round 14
// speedup vs baseline: 1.3579x; 1.3579x over previous
#include <cuda_runtime.h>
#include <cuda_bf16.h>
#include <cstdint>

// ---------------- problem constants ----------------
#define B_   16
#define C_   64
#define H_   192
#define W_   192
#define NPIX (H_ * W_)

// ---------------- tiling (R5 exact) ----------------
#define TR 8                 // tile rows
#define TC 32                // tile cols  (256 px, 64 oc per tile)
#define HR 10                // halo rows
#define HC 34                // halo cols

// smem x layout per image: [slot = kf*4+p (16)][row (10)][col (34)][pair (2 words)]
#define ROWB  272            // 34 * 8 bytes per row
#define SLOTB 2720           // 10 * 272
#define IMGB  (16 * SLOTB)   // 43520 bytes per image
#define SMEM_BYTES (2 * IMGB) // 87040 (hi, then lo) -> 2 CTAs/SM

// Pre-packed W fragments: [b][tap][kf][hl][mf][lane] uint4 (mma A-frag order)
__device__ uint4 g_wfrag[B_ * 9 * 4 * 2 * 4 * 32];

// ---------------- helpers ----------------
__device__ __forceinline__ uint32_t smem_u32(const void* p) {
    uint32_t a;
    asm("{ .reg .u64 t; cvta.to.shared.u64 t, %1; cvt.u32.u64 %0, t; }" : "=r"(a) : "l"(p));
    return a;
}
__device__ __forceinline__ uint32_t cvt2(float lo, float hi) {
    uint32_t r;
    asm("cvt.rn.satfinite.bf16x2.f32 %0, %1, %2;" : "=r"(r) : "f"(hi), "f"(lo));
    return r;
}
__device__ __forceinline__ void split2(float v0, float v1, uint32_t& h2, uint32_t& l2) {
    h2 = cvt2(v0, v1);
    float h0 = __uint_as_float(h2 << 16);
    float h1 = __uint_as_float(h2 & 0xFFFF0000u);
    l2 = cvt2(v0 - h0, v1 - h1);
}
__device__ __forceinline__ void sts32(uint32_t a, uint32_t v) {
    asm volatile("st.shared.b32 [%0], %1;" :: "r"(a), "r"(v) : "memory");
}
__device__ __forceinline__ void mma16816(float* c, const uint4& a, uint32_t b0, uint32_t b1) {
    asm volatile(
        "mma.sync.aligned.m16n8k16.row.col.f32.bf16.bf16.f32 "
        "{%0,%1,%2,%3}, {%4,%5,%6,%7}, {%8,%9}, {%0,%1,%2,%3};"
        : "+f"(c[0]), "+f"(c[1]), "+f"(c[2]), "+f"(c[3])
        : "r"(a.x), "r"(a.y), "r"(a.z), "r"(a.w), "r"(b0), "r"(b1));
}

// ---------------- prep: interpolate + split + pack W fragments ----------------
__global__ void prep_w(const float* __restrict__ W0, const float* __restrict__ W1,
                       const float* __restrict__ DoT)
{
    const int tap = blockIdx.x;
    const int b   = blockIdx.y;
    const float d = DoT[b], od = 1.0f - d;

    const int t    = threadIdx.x;
    const int kf   = t >> 7;
    const int mf   = (t >> 5) & 3;
    const int lane = t & 31;
    const int m    = mf * 16 + (lane >> 2);
    const int k    = kf * 16 + (lane & 3) * 2;

    float v[4][2];
    #pragma unroll
    for (int r = 0; r < 4; r++) {
        const int oc = m + (r & 1) * 8;
        const int ci = k + (r >> 1) * 8;
        const size_t g0 = (size_t)(oc * C_ + ci) * 9 + tap;
        v[r][0] = od * W0[g0] + d * W1[g0];
        v[r][1] = od * W0[g0 + 9] + d * W1[g0 + 9];
    }
    uint4 hi, lo;
    uint32_t* hp = &hi.x;
    uint32_t* lp = &lo.x;
    #pragma unroll
    for (int r = 0; r < 4; r++) split2(v[r][0], v[r][1], hp[r], lp[r]);

    const size_t base = ((((size_t)(b * 9 + tap) * 4 + kf) * 2) * 4 + mf) * 32 + lane;
    g_wfrag[base]       = hi;
    g_wfrag[base + 128] = lo;
}

// ---------------- main kernel (R5 + vectorized fill) ----------------
__global__ __launch_bounds__(256, 2)
void conv_mma(const float* __restrict__ x, float* __restrict__ y)
{
    extern __shared__ char smem[];
    const uint32_t sx = smem_u32(smem);

    const int tid  = threadIdx.x;
    const int wid  = tid >> 5;          // warp = tile row (0..7)
    const int lane = tid & 31;
    const int p_   = lane & 3;
    const int q    = lane >> 2;
    const int b    = blockIdx.y;
    const int py0  = (blockIdx.x / 6) * TR;
    const int px0  = (blockIdx.x % 6) * TC;

    const float* xb = x + (size_t)b * C_ * NPIX;

    // ---- fill smem: aligned float4 block loads -> bf16 hi/lo split ----
    // Blocks: ci2 (32) x r (10) x blk (10). Block blk covers gx [px0-4+4*blk .. +3],
    // which is fully in [0,192) or fully out (W%4==0). Column c0 = 4*blk - 3.
    {
        const int hy0  = py0 - 1;
        const int gxb0 = px0 - 4;
        for (int idx = tid; idx < 32 * 10 * 10; idx += 256) {
            const int ci2 = idx / 100;
            const int rem = idx - ci2 * 100;
            const int r   = rem / 10;
            const int blk = rem - r * 10;
            const int gy  = hy0 + r;
            const int gxb = gxb0 + blk * 4;

            float4 va = make_float4(0.f, 0.f, 0.f, 0.f);
            float4 vb = make_float4(0.f, 0.f, 0.f, 0.f);
            if ((unsigned)gy < H_ && (unsigned)gxb <= (unsigned)(W_ - 4)) {
                const float* p = xb + (size_t)(2 * ci2) * NPIX + gy * W_ + gxb;
                va = *(const float4*)p;
                vb = *(const float4*)(p + NPIX);
            }

            const int kfi = ci2 >> 3, l = ci2 & 7, pp = l & 3, e = l >> 2;
            const uint32_t base = (uint32_t)((kfi * 4 + pp) * SLOTB + r * ROWB + e * 4);
            const int c0 = 4 * blk - 3;
            const float* ap = &va.x;
            const float* bp = &vb.x;
            #pragma unroll
            for (int j = 0; j < 4; j++) {
                const int c = c0 + j;
                if ((unsigned)c < 34u) {
                    uint32_t h2, l2;
                    split2(ap[j], bp[j], h2, l2);
                    sts32(sx + base + (uint32_t)c * 8, h2);
                    sts32(sx + IMGB + base + (uint32_t)c * 8, l2);
                }
            }
        }
    }
    __syncthreads();

    float acc[4][4][4];
    #pragma unroll
    for (int mf = 0; mf < 4; mf++)
        #pragma unroll
        for (int cs = 0; cs < 4; cs++) {
            acc[mf][cs][0] = 0.f; acc[mf][cs][1] = 0.f;
            acc[mf][cs][2] = 0.f; acc[mf][cs][3] = 0.f;
        }

    const uint4* wf = g_wfrag + (size_t)(b * 9) * 1024;
    const uint32_t thr_base = sx + (uint32_t)(p_ * SLOTB + q * 8);

    for (int tap = 0; tap < 9; tap++) {
        const int ky = tap / 3;
        const int kx = tap - ky * 3;
        const uint32_t tap_off = (uint32_t)((wid + ky) * ROWB + kx * 8);
        const uint4* wft = wf + tap * 1024;

        #pragma unroll
        for (int kf = 0; kf < 4; kf++) {
            const uint4* wfk = wft + kf * 256;
            uint4 ah[4], al[4];
            #pragma unroll
            for (int mf = 0; mf < 4; mf++) {
                ah[mf] = wfk[mf * 32 + lane];
                al[mf] = wfk[128 + mf * 32 + lane];
            }
            const uint32_t a_base = thr_base + tap_off + (uint32_t)(kf * 4 * SLOTB);

            #pragma unroll
            for (int cs = 0; cs < 4; cs++) {
                const uint32_t addr = a_base + cs * 64;
                uint32_t bh0, bh1, bl0, bl1;
                asm volatile("ld.shared.v2.b32 {%0,%1}, [%2];"
                             : "=r"(bh0), "=r"(bh1) : "r"(addr));
                asm volatile("ld.shared.v2.b32 {%0,%1}, [%2];"
                             : "=r"(bl0), "=r"(bl1) : "r"(addr + IMGB));
                #pragma unroll
                for (int mf = 0; mf < 4; mf++) mma16816(acc[mf][cs], ah[mf], bh0, bh1);
                #pragma unroll
                for (int mf = 0; mf < 4; mf++) mma16816(acc[mf][cs], al[mf], bh0, bh1);
                #pragma unroll
                for (int mf = 0; mf < 4; mf++) mma16816(acc[mf][cs], ah[mf], bl0, bl1);
            }
        }
    }

    // ---- epilogue: D rows = oc, cols = pixels ----
    float* yb = y + (size_t)b * C_ * NPIX;
    const int gy = py0 + wid;
    #pragma unroll
    for (int mf = 0; mf < 4; mf++) {
        const int oc = mf * 16 + q;
        #pragma unroll
        for (int cs = 0; cs < 4; cs++) {
            const int gx = px0 + cs * 8 + p_ * 2;
            float2* o0 = (float2*)(yb + (size_t)oc * NPIX + gy * W_ + gx);
            *o0 = make_float2(acc[mf][cs][0], acc[mf][cs][1]);
            float2* o1 = (float2*)(yb + (size_t)(oc + 8) * NPIX + gy * W_ + gx);
            *o1 = make_float2(acc[mf][cs][2], acc[mf][cs][3]);
        }
    }
}

// ---------------- launch ----------------
extern "C" void kernel_launch(void* const* d_in, const int* in_sizes, int n_in,
                              void* d_out, int out_size)
{
    const float* x   = (const float*)d_in[0];
    const float* DoT = (const float*)d_in[1];
    const float* W0  = (const float*)d_in[2];
    const float* W1  = (const float*)d_in[3];
    float* y = (float*)d_out;

    cudaFuncSetAttribute(conv_mma, cudaFuncAttributeMaxDynamicSharedMemorySize, SMEM_BYTES);

    prep_w<<<dim3(9, B_), 512>>>(W0, W1, DoT);
    conv_mma<<<dim3((H_ / TR) * (W_ / TC), B_), 256, SMEM_BYTES>>>(x, y);
}

// round 15
// speedup vs baseline: 1.6998x; 1.2518x over previous
#include <cuda_runtime.h>
#include <cuda_fp16.h>
#include <cstdint>

// ---------------- problem constants ----------------
#define B_   16
#define C_   64
#define H_   192
#define W_   192
#define NPIX (H_ * W_)

// ---------------- tiling (R14 exact) ----------------
#define TR 8                 // tile rows
#define TC 32                // tile cols  (256 px, 64 oc per tile)
#define HR 10                // halo rows
#define HC 34                // halo cols

// smem x layout per image: [slot = kf*4+p (16)][row (10)][col (34)][pair (2 words)]
#define ROWB  272            // 34 * 8 bytes per row
#define SLOTB 2720           // 10 * 272
#define IMGB  (16 * SLOTB)   // 43520 bytes per image
#define SMEM_BYTES (2 * IMGB) // 87040 (hi, then lo) -> 2 CTAs/SM

// Pre-packed W fragments (fp16, single set): [b][tap][kf][mf][lane] uint4
__device__ uint4 g_wfrag[B_ * 9 * 4 * 4 * 32];

// ---------------- helpers ----------------
__device__ __forceinline__ uint32_t smem_u32(const void* p) {
    uint32_t a;
    asm("{ .reg .u64 t; cvta.to.shared.u64 t, %1; cvt.u32.u64 %0, t; }" : "=r"(a) : "l"(p));
    return a;
}
// pack two fp32 -> fp16x2 (low half = v0)
__device__ __forceinline__ uint32_t cvtf16x2(float v0, float v1) {
    uint32_t r;
    asm("cvt.rn.f16x2.f32 %0, %1, %2;" : "=r"(r) : "f"(v1), "f"(v0));
    return r;
}
// fp16 hi/lo split of two fp32 values
__device__ __forceinline__ void splitf16(float v0, float v1, uint32_t& h2, uint32_t& l2) {
    __half h0 = __float2half_rn(v0);
    __half h1 = __float2half_rn(v1);
    h2 = ((uint32_t)__half_as_ushort(h1) << 16) | (uint32_t)__half_as_ushort(h0);
    float r0 = v0 - __half2float(h0);
    float r1 = v1 - __half2float(h1);
    l2 = cvtf16x2(r0, r1);
}
__device__ __forceinline__ void sts32(uint32_t a, uint32_t v) {
    asm volatile("st.shared.b32 [%0], %1;" :: "r"(a), "r"(v) : "memory");
}
__device__ __forceinline__ void mma16816(float* c, const uint4& a, uint32_t b0, uint32_t b1) {
    asm volatile(
        "mma.sync.aligned.m16n8k16.row.col.f32.f16.f16.f32 "
        "{%0,%1,%2,%3}, {%4,%5,%6,%7}, {%8,%9}, {%0,%1,%2,%3};"
        : "+f"(c[0]), "+f"(c[1]), "+f"(c[2]), "+f"(c[3])
        : "r"(a.x), "r"(a.y), "r"(a.z), "r"(a.w), "r"(b0), "r"(b1));
}

// ---------------- prep: interpolate + fp16 round + pack W fragments ----------------
__global__ void prep_w(const float* __restrict__ W0, const float* __restrict__ W1,
                       const float* __restrict__ DoT)
{
    const int tap = blockIdx.x;
    const int b   = blockIdx.y;
    const float d = DoT[b], od = 1.0f - d;

    const int t    = threadIdx.x;
    const int kf   = t >> 7;
    const int mf   = (t >> 5) & 3;
    const int lane = t & 31;
    const int m    = mf * 16 + (lane >> 2);
    const int k    = kf * 16 + (lane & 3) * 2;

    // mma A-frag reg order: r0=(m,k..k+1) r1=(m+8,k..) r2=(m,k+8..) r3=(m+8,k+8..)
    uint4 hi;
    uint32_t* hp = &hi.x;
    #pragma unroll
    for (int r = 0; r < 4; r++) {
        const int oc = m + (r & 1) * 8;
        const int ci = k + (r >> 1) * 8;
        const size_t g0 = (size_t)(oc * C_ + ci) * 9 + tap;
        float v0 = od * W0[g0] + d * W1[g0];
        float v1 = od * W0[g0 + 9] + d * W1[g0 + 9];
        hp[r] = cvtf16x2(v0, v1);
    }

    const size_t base = (((size_t)(b * 9 + tap) * 4 + kf) * 4 + mf) * 32 + lane;
    g_wfrag[base] = hi;
}

// ---------------- main kernel (R14 structure, fp16 2-term) ----------------
__global__ __launch_bounds__(256, 2)
void conv_mma(const float* __restrict__ x, float* __restrict__ y)
{
    extern __shared__ char smem[];
    const uint32_t sx = smem_u32(smem);

    const int tid  = threadIdx.x;
    const int wid  = tid >> 5;          // warp = tile row (0..7)
    const int lane = tid & 31;
    const int p_   = lane & 3;
    const int q    = lane >> 2;
    const int b    = blockIdx.y;
    const int py0  = (blockIdx.x / 6) * TR;
    const int px0  = (blockIdx.x % 6) * TC;

    const float* xb = x + (size_t)b * C_ * NPIX;

    // ---- fill smem: aligned float4 block loads -> fp16 hi/lo split ----
    {
        const int hy0  = py0 - 1;
        const int gxb0 = px0 - 4;
        for (int idx = tid; idx < 32 * 10 * 10; idx += 256) {
            const int ci2 = idx / 100;
            const int rem = idx - ci2 * 100;
            const int r   = rem / 10;
            const int blk = rem - r * 10;
            const int gy  = hy0 + r;
            const int gxb = gxb0 + blk * 4;

            float4 va = make_float4(0.f, 0.f, 0.f, 0.f);
            float4 vb = make_float4(0.f, 0.f, 0.f, 0.f);
            if ((unsigned)gy < H_ && (unsigned)gxb <= (unsigned)(W_ - 4)) {
                const float* p = xb + (size_t)(2 * ci2) * NPIX + gy * W_ + gxb;
                va = *(const float4*)p;
                vb = *(const float4*)(p + NPIX);
            }

            const int kfi = ci2 >> 3, l = ci2 & 7, pp = l & 3, e = l >> 2;
            const uint32_t base = (uint32_t)((kfi * 4 + pp) * SLOTB + r * ROWB + e * 4);
            const int c0 = 4 * blk - 3;
            const float* ap = &va.x;
            const float* bp = &vb.x;
            #pragma unroll
            for (int j = 0; j < 4; j++) {
                const int c = c0 + j;
                if ((unsigned)c < 34u) {
                    uint32_t h2, l2;
                    splitf16(ap[j], bp[j], h2, l2);
                    sts32(sx + base + (uint32_t)c * 8, h2);
                    sts32(sx + IMGB + base + (uint32_t)c * 8, l2);
                }
            }
        }
    }
    __syncthreads();

    float acc[4][4][4];
    #pragma unroll
    for (int mf = 0; mf < 4; mf++)
        #pragma unroll
        for (int cs = 0; cs < 4; cs++) {
            acc[mf][cs][0] = 0.f; acc[mf][cs][1] = 0.f;
            acc[mf][cs][2] = 0.f; acc[mf][cs][3] = 0.f;
        }

    const uint4* wf = g_wfrag + (size_t)(b * 9) * 512;
    const uint32_t thr_base = sx + (uint32_t)(p_ * SLOTB + q * 8);

    for (int tap = 0; tap < 9; tap++) {
        const int ky = tap / 3;
        const int kx = tap - ky * 3;
        const uint32_t tap_off = (uint32_t)((wid + ky) * ROWB + kx * 8);
        const uint4* wft = wf + tap * 512;

        #pragma unroll
        for (int kf = 0; kf < 4; kf++) {
            const uint4* wfk = wft + kf * 128;
            uint4 ah[4];
            #pragma unroll
            for (int mf = 0; mf < 4; mf++)
                ah[mf] = wfk[mf * 32 + lane];
            const uint32_t a_base = thr_base + tap_off + (uint32_t)(kf * 4 * SLOTB);

            #pragma unroll
            for (int cs = 0; cs < 4; cs++) {
                const uint32_t addr = a_base + cs * 64;
                uint32_t bh0, bh1, bl0, bl1;
                asm volatile("ld.shared.v2.b32 {%0,%1}, [%2];"
                             : "=r"(bh0), "=r"(bh1) : "r"(addr));
                asm volatile("ld.shared.v2.b32 {%0,%1}, [%2];"
                             : "=r"(bl0), "=r"(bl1) : "r"(addr + IMGB));
                #pragma unroll
                for (int mf = 0; mf < 4; mf++) mma16816(acc[mf][cs], ah[mf], bh0, bh1);
                #pragma unroll
                for (int mf = 0; mf < 4; mf++) mma16816(acc[mf][cs], ah[mf], bl0, bl1);
            }
        }
    }

    // ---- epilogue: D rows = oc, cols = pixels ----
    float* yb = y + (size_t)b * C_ * NPIX;
    const int gy = py0 + wid;
    #pragma unroll
    for (int mf = 0; mf < 4; mf++) {
        const int oc = mf * 16 + q;
        #pragma unroll
        for (int cs = 0; cs < 4; cs++) {
            const int gx = px0 + cs * 8 + p_ * 2;
            float2* o0 = (float2*)(yb + (size_t)oc * NPIX + gy * W_ + gx);
            *o0 = make_float2(acc[mf][cs][0], acc[mf][cs][1]);
            float2* o1 = (float2*)(yb + (size_t)(oc + 8) * NPIX + gy * W_ + gx);
            *o1 = make_float2(acc[mf][cs][2], acc[mf][cs][3]);
        }
    }
}

// ---------------- launch ----------------
extern "C" void kernel_launch(void* const* d_in, const int* in_sizes, int n_in,
                              void* d_out, int out_size)
{
    const float* x   = (const float*)d_in[0];
    const float* DoT = (const float*)d_in[1];
    const float* W0  = (const float*)d_in[2];
    const float* W1  = (const float*)d_in[3];
    float* y = (float*)d_out;

    cudaFuncSetAttribute(conv_mma, cudaFuncAttributeMaxDynamicSharedMemorySize, SMEM_BYTES);

    prep_w<<<dim3(9, B_), 512>>>(W0, W1, DoT);
    conv_mma<<<dim3((H_ / TR) * (W_ / TC), B_), 256, SMEM_BYTES>>>(x, y);
}

// round 16
// speedup vs baseline: 2.3438x; 1.3789x over previous
#include <cuda_runtime.h>
#include <cuda_fp16.h>
#include <cstdint>

// ---------------- problem constants ----------------
#define B_   16
#define C_   64
#define H_   192
#define W_   192
#define NPIX (H_ * W_)

// ---------------- tiling (R15 exact) ----------------
#define TR 8                 // tile rows
#define TC 32                // tile cols  (256 px, 64 oc per tile)
#define HR 10                // halo rows
#define HC 34                // halo cols

// smem x layout (single fp16 image): [slot = kf*4+p (16)][row (10)][col (34)][pair]
#define ROWB  272            // 34 * 8 bytes per row
#define SLOTB 2720           // 10 * 272
#define IMGB  (16 * SLOTB)   // 43520 bytes
#define SMEM_BYTES IMGB      // -> 2+ CTAs/SM (regs-capped at 2)

// Pre-packed W fragments (fp16): [b][tap][kf][mf][lane] uint4
__device__ uint4 g_wfrag[B_ * 9 * 4 * 4 * 32];

// ---------------- helpers ----------------
__device__ __forceinline__ uint32_t smem_u32(const void* p) {
    uint32_t a;
    asm("{ .reg .u64 t; cvta.to.shared.u64 t, %1; cvt.u32.u64 %0, t; }" : "=r"(a) : "l"(p));
    return a;
}
// pack two fp32 -> fp16x2 (low half = v0)
__device__ __forceinline__ uint32_t cvtf16x2(float v0, float v1) {
    uint32_t r;
    asm("cvt.rn.f16x2.f32 %0, %1, %2;" : "=r"(r) : "f"(v1), "f"(v0));
    return r;
}
__device__ __forceinline__ void sts32(uint32_t a, uint32_t v) {
    asm volatile("st.shared.b32 [%0], %1;" :: "r"(a), "r"(v) : "memory");
}
__device__ __forceinline__ void mma16816(float* c, const uint4& a, uint32_t b0, uint32_t b1) {
    asm volatile(
        "mma.sync.aligned.m16n8k16.row.col.f32.f16.f16.f32 "
        "{%0,%1,%2,%3}, {%4,%5,%6,%7}, {%8,%9}, {%0,%1,%2,%3};"
        : "+f"(c[0]), "+f"(c[1]), "+f"(c[2]), "+f"(c[3])
        : "r"(a.x), "r"(a.y), "r"(a.z), "r"(a.w), "r"(b0), "r"(b1));
}

// ---------------- prep: interpolate + fp16 round + pack W fragments ----------------
__global__ void prep_w(const float* __restrict__ W0, const float* __restrict__ W1,
                       const float* __restrict__ DoT)
{
    const int tap = blockIdx.x;
    const int b   = blockIdx.y;
    const float d = DoT[b], od = 1.0f - d;

    const int t    = threadIdx.x;
    const int kf   = t >> 7;
    const int mf   = (t >> 5) & 3;
    const int lane = t & 31;
    const int m    = mf * 16 + (lane >> 2);
    const int k    = kf * 16 + (lane & 3) * 2;

    uint4 hi;
    uint32_t* hp = &hi.x;
    #pragma unroll
    for (int r = 0; r < 4; r++) {
        const int oc = m + (r & 1) * 8;
        const int ci = k + (r >> 1) * 8;
        const size_t g0 = (size_t)(oc * C_ + ci) * 9 + tap;
        float v0 = od * W0[g0] + d * W1[g0];
        float v1 = od * W0[g0 + 9] + d * W1[g0 + 9];
        hp[r] = cvtf16x2(v0, v1);
    }

    const size_t base = (((size_t)(b * 9 + tap) * 4 + kf) * 4 + mf) * 32 + lane;
    g_wfrag[base] = hi;
}

// ---------------- main kernel (R15 structure, fp16 single-term) ----------------
__global__ __launch_bounds__(256, 2)
void conv_mma(const float* __restrict__ x, float* __restrict__ y)
{
    extern __shared__ char smem[];
    const uint32_t sx = smem_u32(smem);

    const int tid  = threadIdx.x;
    const int wid  = tid >> 5;          // warp = tile row (0..7)
    const int lane = tid & 31;
    const int p_   = lane & 3;
    const int q    = lane >> 2;
    const int b    = blockIdx.y;
    const int py0  = (blockIdx.x / 6) * TR;
    const int px0  = (blockIdx.x % 6) * TC;

    const float* xb = x + (size_t)b * C_ * NPIX;

    // ---- fill smem: aligned float4 block loads -> fp16 ----
    {
        const int hy0  = py0 - 1;
        const int gxb0 = px0 - 4;
        for (int idx = tid; idx < 32 * 10 * 10; idx += 256) {
            const int ci2 = idx / 100;
            const int rem = idx - ci2 * 100;
            const int r   = rem / 10;
            const int blk = rem - r * 10;
            const int gy  = hy0 + r;
            const int gxb = gxb0 + blk * 4;

            float4 va = make_float4(0.f, 0.f, 0.f, 0.f);
            float4 vb = make_float4(0.f, 0.f, 0.f, 0.f);
            if ((unsigned)gy < H_ && (unsigned)gxb <= (unsigned)(W_ - 4)) {
                const float* p = xb + (size_t)(2 * ci2) * NPIX + gy * W_ + gxb;
                va = *(const float4*)p;
                vb = *(const float4*)(p + NPIX);
            }

            const int kfi = ci2 >> 3, l = ci2 & 7, pp = l & 3, e = l >> 2;
            const uint32_t base = (uint32_t)((kfi * 4 + pp) * SLOTB + r * ROWB + e * 4);
            const int c0 = 4 * blk - 3;
            const float* ap = &va.x;
            const float* bp = &vb.x;
            #pragma unroll
            for (int j = 0; j < 4; j++) {
                const int c = c0 + j;
                if ((unsigned)c < 34u) {
                    sts32(sx + base + (uint32_t)c * 8, cvtf16x2(ap[j], bp[j]));
                }
            }
        }
    }
    __syncthreads();

    float acc[4][4][4];
    #pragma unroll
    for (int mf = 0; mf < 4; mf++)
        #pragma unroll
        for (int cs = 0; cs < 4; cs++) {
            acc[mf][cs][0] = 0.f; acc[mf][cs][1] = 0.f;
            acc[mf][cs][2] = 0.f; acc[mf][cs][3] = 0.f;
        }

    const uint4* wf = g_wfrag + (size_t)(b * 9) * 512;
    const uint32_t thr_base = sx + (uint32_t)(p_ * SLOTB + q * 8);

    for (int tap = 0; tap < 9; tap++) {
        const int ky = tap / 3;
        const int kx = tap - ky * 3;
        const uint32_t tap_off = (uint32_t)((wid + ky) * ROWB + kx * 8);
        const uint4* wft = wf + tap * 512;

        #pragma unroll
        for (int kf = 0; kf < 4; kf++) {
            const uint4* wfk = wft + kf * 128;
            uint4 ah[4];
            #pragma unroll
            for (int mf = 0; mf < 4; mf++)
                ah[mf] = wfk[mf * 32 + lane];
            const uint32_t a_base = thr_base + tap_off + (uint32_t)(kf * 4 * SLOTB);

            #pragma unroll
            for (int cs = 0; cs < 4; cs++) {
                const uint32_t addr = a_base + cs * 64;
                uint32_t bh0, bh1;
                asm volatile("ld.shared.v2.b32 {%0,%1}, [%2];"
                             : "=r"(bh0), "=r"(bh1) : "r"(addr));
                #pragma unroll
                for (int mf = 0; mf < 4; mf++) mma16816(acc[mf][cs], ah[mf], bh0, bh1);
            }
        }
    }

    // ---- epilogue: D rows = oc, cols = pixels ----
    float* yb = y + (size_t)b * C_ * NPIX;
    const int gy = py0 + wid;
    #pragma unroll
    for (int mf = 0; mf < 4; mf++) {
        const int oc = mf * 16 + q;
        #pragma unroll
        for (int cs = 0; cs < 4; cs++) {
            const int gx = px0 + cs * 8 + p_ * 2;
            float2* o0 = (float2*)(yb + (size_t)oc * NPIX + gy * W_ + gx);
            *o0 = make_float2(acc[mf][cs][0], acc[mf][cs][1]);
            float2* o1 = (float2*)(yb + (size_t)(oc + 8) * NPIX + gy * W_ + gx);
            *o1 = make_float2(acc[mf][cs][2], acc[mf][cs][3]);
        }
    }
}

// ---------------- launch ----------------
extern "C" void kernel_launch(void* const* d_in, const int* in_sizes, int n_in,
                              void* d_out, int out_size)
{
    const float* x   = (const float*)d_in[0];
    const float* DoT = (const float*)d_in[1];
    const float* W0  = (const float*)d_in[2];
    const float* W1  = (const float*)d_in[3];
    float* y = (float*)d_out;

    cudaFuncSetAttribute(conv_mma, cudaFuncAttributeMaxDynamicSharedMemorySize, SMEM_BYTES);

    prep_w<<<dim3(9, B_), 512>>>(W0, W1, DoT);
    conv_mma<<<dim3((H_ / TR) * (W_ / TC), B_), 256, SMEM_BYTES>>>(x, y);
}

// round 17
// speedup vs baseline: 2.4922x; 1.0633x over previous
#include <cuda_runtime.h>
#include <cuda_fp16.h>
#include <cstdint>

// ---------------- problem constants ----------------
#define B_   16
#define C_   64
#define H_   192
#define W_   192
#define NPIX (H_ * W_)

// ---------------- tiling (R16 exact) ----------------
#define TR 8                 // tile rows
#define TC 32                // tile cols  (256 px, 64 oc per tile)
#define HR 10                // halo rows
#define HC 34                // halo cols

// smem x layout (single fp16 image): [slot = kf*4+p (16)][row (10)][col (34)][pair]
#define ROWB  272            // 34 * 8 bytes per row
#define SLOTB 2720           // 10 * 272
#define IMGB  (16 * SLOTB)   // 43520 bytes
#define SMEM_BYTES IMGB

// Pre-packed W fragments (fp16): [b][tap][kf][mf][lane] uint4
__device__ uint4 g_wfrag[B_ * 9 * 4 * 4 * 32];

// ---------------- helpers ----------------
__device__ __forceinline__ uint32_t smem_u32(const void* p) {
    uint32_t a;
    asm("{ .reg .u64 t; cvta.to.shared.u64 t, %1; cvt.u32.u64 %0, t; }" : "=r"(a) : "l"(p));
    return a;
}
__device__ __forceinline__ uint32_t cvtf16x2(float v0, float v1) {
    uint32_t r;
    asm("cvt.rn.f16x2.f32 %0, %1, %2;" : "=r"(r) : "f"(v1), "f"(v0));
    return r;
}
__device__ __forceinline__ void sts32(uint32_t a, uint32_t v) {
    asm volatile("st.shared.b32 [%0], %1;" :: "r"(a), "r"(v) : "memory");
}
__device__ __forceinline__ void mma16816(float* c, const uint4& a, uint32_t b0, uint32_t b1) {
    asm volatile(
        "mma.sync.aligned.m16n8k16.row.col.f32.f16.f16.f32 "
        "{%0,%1,%2,%3}, {%4,%5,%6,%7}, {%8,%9}, {%0,%1,%2,%3};"
        : "+f"(c[0]), "+f"(c[1]), "+f"(c[2]), "+f"(c[3])
        : "r"(a.x), "r"(a.y), "r"(a.z), "r"(a.w), "r"(b0), "r"(b1));
}

// ---------------- prep: interpolate + fp16 round + pack W fragments ----------------
__global__ void prep_w(const float* __restrict__ W0, const float* __restrict__ W1,
                       const float* __restrict__ DoT)
{
    const int tap = blockIdx.x;
    const int b   = blockIdx.y;
    const float d = DoT[b], od = 1.0f - d;

    const int t    = threadIdx.x;
    const int kf   = t >> 7;
    const int mf   = (t >> 5) & 3;
    const int lane = t & 31;
    const int m    = mf * 16 + (lane >> 2);
    const int k    = kf * 16 + (lane & 3) * 2;

    uint4 hi;
    uint32_t* hp = &hi.x;
    #pragma unroll
    for (int r = 0; r < 4; r++) {
        const int oc = m + (r & 1) * 8;
        const int ci = k + (r >> 1) * 8;
        const size_t g0 = (size_t)(oc * C_ + ci) * 9 + tap;
        float v0 = od * W0[g0] + d * W1[g0];
        float v1 = od * W0[g0 + 9] + d * W1[g0 + 9];
        hp[r] = cvtf16x2(v0, v1);
    }

    const size_t base = (((size_t)(b * 9 + tap) * 4 + kf) * 4 + mf) * 32 + lane;
    g_wfrag[base] = hi;
}

// load wf block g (4 uint4) into register buffer A
#define LOADW(A, g)                                    \
    do {                                               \
        const uint4* _p = wf + (g) * 128 + lane;       \
        (A)[0] = _p[0];                                \
        (A)[1] = _p[32];                               \
        (A)[2] = _p[64];                               \
        (A)[3] = _p[96];                               \
    } while (0)

// compute block (tap, kf) from register buffer A
#define COMPUTE(A, tap, kf)                                                     \
    do {                                                                        \
        const uint32_t a_base = thr_base +                                      \
            (uint32_t)((wid + (tap) / 3) * ROWB + ((tap) % 3) * 8 +             \
                       (kf) * 4 * SLOTB);                                       \
        _Pragma("unroll")                                                       \
        for (int cs = 0; cs < 4; cs++) {                                        \
            uint32_t bh0, bh1;                                                  \
            asm volatile("ld.shared.v2.b32 {%0,%1}, [%2];"                      \
                         : "=r"(bh0), "=r"(bh1) : "r"(a_base + cs * 64));       \
            mma16816(acc[0][cs], (A)[0], bh0, bh1);                             \
            mma16816(acc[1][cs], (A)[1], bh0, bh1);                             \
            mma16816(acc[2][cs], (A)[2], bh0, bh1);                             \
            mma16816(acc[3][cs], (A)[3], bh0, bh1);                             \
        }                                                                       \
    } while (0)

// ---------------- main kernel (R16 + wf register double-buffering) ----------------
__global__ __launch_bounds__(256, 2)
void conv_mma(const float* __restrict__ x, float* __restrict__ y)
{
    extern __shared__ char smem[];
    const uint32_t sx = smem_u32(smem);

    const int tid  = threadIdx.x;
    const int wid  = tid >> 5;          // warp = tile row (0..7)
    const int lane = tid & 31;
    const int p_   = lane & 3;
    const int q    = lane >> 2;
    const int b    = blockIdx.y;
    const int py0  = (blockIdx.x / 6) * TR;
    const int px0  = (blockIdx.x % 6) * TC;

    const float* xb = x + (size_t)b * C_ * NPIX;
    const uint4* wf = g_wfrag + (size_t)(b * 9) * 512;

    // ---- fill smem: aligned float4 block loads -> fp16 ----
    {
        const int hy0  = py0 - 1;
        const int gxb0 = px0 - 4;
        for (int idx = tid; idx < 32 * 10 * 10; idx += 256) {
            const int ci2 = idx / 100;
            const int rem = idx - ci2 * 100;
            const int r   = rem / 10;
            const int blk = rem - r * 10;
            const int gy  = hy0 + r;
            const int gxb = gxb0 + blk * 4;

            float4 va = make_float4(0.f, 0.f, 0.f, 0.f);
            float4 vb = make_float4(0.f, 0.f, 0.f, 0.f);
            if ((unsigned)gy < H_ && (unsigned)gxb <= (unsigned)(W_ - 4)) {
                const float* p = xb + (size_t)(2 * ci2) * NPIX + gy * W_ + gxb;
                va = *(const float4*)p;
                vb = *(const float4*)(p + NPIX);
            }

            const int kfi = ci2 >> 3, l = ci2 & 7, pp = l & 3, e = l >> 2;
            const uint32_t base = (uint32_t)((kfi * 4 + pp) * SLOTB + r * ROWB + e * 4);
            const int c0 = 4 * blk - 3;
            const float* ap = &va.x;
            const float* bp = &vb.x;
            #pragma unroll
            for (int j = 0; j < 4; j++) {
                const int c = c0 + j;
                if ((unsigned)c < 34u) {
                    sts32(sx + base + (uint32_t)c * 8, cvtf16x2(ap[j], bp[j]));
                }
            }
        }
    }

    // prologue prefetch of block 0 overlaps the fill's tail
    uint4 a0[4], a1[4];
    LOADW(a0, 0);

    __syncthreads();

    float acc[4][4][4];
    #pragma unroll
    for (int mf = 0; mf < 4; mf++)
        #pragma unroll
        for (int cs = 0; cs < 4; cs++) {
            acc[mf][cs][0] = 0.f; acc[mf][cs][1] = 0.f;
            acc[mf][cs][2] = 0.f; acc[mf][cs][3] = 0.f;
        }

    const uint32_t thr_base = sx + (uint32_t)(p_ * SLOTB + q * 8);

    // ---- mainloop: 36 blocks, fully unrolled, double-buffered wf ----
    #pragma unroll
    for (int g = 0; g < 36; g++) {
        const int tap = g >> 2;
        const int kf  = g & 3;
        const int gn  = (g + 1 < 36) ? (g + 1) : 0;   // wrap: next tile reuses
        if ((g & 1) == 0) {
            LOADW(a1, gn);
            COMPUTE(a0, tap, kf);
        } else {
            LOADW(a0, gn);
            COMPUTE(a1, tap, kf);
        }
    }

    // ---- epilogue: D rows = oc, cols = pixels ----
    float* yb = y + (size_t)b * C_ * NPIX;
    const int gy = py0 + wid;
    #pragma unroll
    for (int mf = 0; mf < 4; mf++) {
        const int oc = mf * 16 + q;
        #pragma unroll
        for (int cs = 0; cs < 4; cs++) {
            const int gx = px0 + cs * 8 + p_ * 2;
            float2* o0 = (float2*)(yb + (size_t)oc * NPIX + gy * W_ + gx);
            *o0 = make_float2(acc[mf][cs][0], acc[mf][cs][1]);
            float2* o1 = (float2*)(yb + (size_t)(oc + 8) * NPIX + gy * W_ + gx);
            *o1 = make_float2(acc[mf][cs][2], acc[mf][cs][3]);
        }
    }
}

// ---------------- launch ----------------
extern "C" void kernel_launch(void* const* d_in, const int* in_sizes, int n_in,
                              void* d_out, int out_size)
{
    const float* x   = (const float*)d_in[0];
    const float* DoT = (const float*)d_in[1];
    const float* W0  = (const float*)d_in[2];
    const float* W1  = (const float*)d_in[3];
    float* y = (float*)d_out;

    cudaFuncSetAttribute(conv_mma, cudaFuncAttributeMaxDynamicSharedMemorySize, SMEM_BYTES);

    prep_w<<<dim3(9, B_), 512>>>(W0, W1, DoT);
    conv_mma<<<dim3((H_ / TR) * (W_ / TC), B_), 256, SMEM_BYTES>>>(x, y);
}